// round 15
// baseline (speedup 1.0000x reference)
#include <cuda_runtime.h>
#include <cuda_bf16.h>
#include <cstdint>

// Problem constants
#define BATCH   1024
#define SEQLEN  128
#define NFEAT   256
#define NHID    30
#define NGATE   120          // 4*NHID
#define MROWS   (BATCH*SEQLEN)   // 131072
#define NB      8            // batch elements per recurrent CTA (this round)

__device__ float g_xg0[(size_t)MROWS * NGATE];
__device__ __nv_bfloat16 g_whi[128 * NFEAT];
__device__ __nv_bfloat16 g_wlo[128 * NFEAT];

// ---------------------------------------------------------------------------
// packed f32x2 helpers (sm_103a FFMA2 — only reachable via PTX)
// ---------------------------------------------------------------------------
__device__ __forceinline__ void ffma2(uint64_t& d, uint64_t a, uint64_t b) {
    asm("fma.rn.f32x2 %0, %1, %2, %0;" : "+l"(d) : "l"(a), "l"(b));
}
__device__ __forceinline__ uint64_t pack2(float lo, float hi) {
    uint64_t r;
    asm("mov.b64 %0, {%1,%2};" : "=l"(r) : "f"(lo), "f"(hi));
    return r;
}
__device__ __forceinline__ float2 unpack2(uint64_t v) {
    float2 r;
    asm("mov.b64 {%0,%1}, %2;" : "=f"(r.x), "=f"(r.y) : "l"(v));
    return r;
}

// ---------------------------------------------------------------------------
// Kernel 0: one-shot conversion of w_ih0 -> split bf16, vectorized x4
// ---------------------------------------------------------------------------
__global__ __launch_bounds__(256) void wcvt(const float* __restrict__ w) {
    int t4 = blockIdx.x * 256 + threadIdx.x;
    int base = t4 * 4;
    int n = base >> 8;
    int k = base & 255;
    float4 v = make_float4(0.f, 0.f, 0.f, 0.f);
    if (n < NGATE)
        v = *reinterpret_cast<const float4*>(w + n * NFEAT + k);
    uint32_t bx = __float_as_uint(v.x), by = __float_as_uint(v.y);
    uint32_t bz = __float_as_uint(v.z), bw = __float_as_uint(v.w);
    uint2 hi;
    hi.x = __byte_perm(bx, by, 0x7632);
    hi.y = __byte_perm(bz, bw, 0x7632);
    float lx = v.x - __uint_as_float(bx & 0xffff0000u);
    float ly = v.y - __uint_as_float(by & 0xffff0000u);
    float lz = v.z - __uint_as_float(bz & 0xffff0000u);
    float lw = v.w - __uint_as_float(bw & 0xffff0000u);
    __nv_bfloat162 l01 = __floats2bfloat162_rn(lx, ly);
    __nv_bfloat162 l23 = __floats2bfloat162_rn(lz, lw);
    uint2 lo;
    lo.x = *reinterpret_cast<uint32_t*>(&l01);
    lo.y = *reinterpret_cast<uint32_t*>(&l23);
    *reinterpret_cast<uint2*>(&g_whi[base]) = hi;
    *reinterpret_cast<uint2*>(&g_wlo[base]) = lo;
}

// ---------------------------------------------------------------------------
// Kernel 1: xg0 = x @ w_ih0^T + bias -- split-bf16 tensor core, double-buffered
// (round-10 verified config; unchanged)
// ---------------------------------------------------------------------------
#define BK     32
#define SAS    40

__device__ __forceinline__ uint32_t smem_u32(const void* p) {
    return (uint32_t)__cvta_generic_to_shared(p);
}
__device__ __forceinline__ void ldm_x4(uint32_t addr, uint32_t& r0, uint32_t& r1,
                                       uint32_t& r2, uint32_t& r3) {
    asm volatile("ldmatrix.sync.aligned.m8n8.x4.shared.b16 {%0,%1,%2,%3}, [%4];"
                 : "=r"(r0), "=r"(r1), "=r"(r2), "=r"(r3) : "r"(addr));
}
__device__ __forceinline__ void ldm_x2(uint32_t addr, uint32_t& r0, uint32_t& r1) {
    asm volatile("ldmatrix.sync.aligned.m8n8.x2.shared.b16 {%0,%1}, [%2];"
                 : "=r"(r0), "=r"(r1) : "r"(addr));
}
__device__ __forceinline__ void mma_bf16(float* c, const uint32_t* a, const uint32_t* b) {
    asm volatile(
        "mma.sync.aligned.m16n8k16.row.col.f32.bf16.bf16.f32 "
        "{%0,%1,%2,%3}, {%4,%5,%6,%7}, {%8,%9}, {%0,%1,%2,%3};"
        : "+f"(c[0]), "+f"(c[1]), "+f"(c[2]), "+f"(c[3])
        : "r"(a[0]), "r"(a[1]), "r"(a[2]), "r"(a[3]), "r"(b[0]), "r"(b[1]));
}
__device__ __forceinline__ void cvt_hilo(float4 v, uint2& hi, uint2& lo) {
    uint32_t bx = __float_as_uint(v.x), by = __float_as_uint(v.y);
    uint32_t bz = __float_as_uint(v.z), bw = __float_as_uint(v.w);
    hi.x = __byte_perm(bx, by, 0x7632);
    hi.y = __byte_perm(bz, bw, 0x7632);
    float lx = v.x - __uint_as_float(bx & 0xffff0000u);
    float ly = v.y - __uint_as_float(by & 0xffff0000u);
    float lz = v.z - __uint_as_float(bz & 0xffff0000u);
    float lw = v.w - __uint_as_float(bw & 0xffff0000u);
    __nv_bfloat162 l01 = __floats2bfloat162_rn(lx, ly);
    __nv_bfloat162 l23 = __floats2bfloat162_rn(lz, lw);
    lo.x = *reinterpret_cast<uint32_t*>(&l01);
    lo.y = *reinterpret_cast<uint32_t*>(&l23);
}

__global__ __launch_bounds__(256, 2) void gemm_xg0_tc(
    const float* __restrict__ x,
    const float* __restrict__ b_ih,
    const float* __restrict__ b_hh)
{
    __shared__ __nv_bfloat16 sAhi[2][128 * SAS];
    __shared__ __nv_bfloat16 sAlo[2][128 * SAS];
    __shared__ __nv_bfloat16 sBhi[2][128 * SAS];
    __shared__ __nv_bfloat16 sBlo[2][128 * SAS];

    const int tid  = threadIdx.x;
    const int lane = tid & 31;
    const int wid  = tid >> 5;
    const int m0   = blockIdx.x * 128;

    const int wm = wid & 1;
    const int wn = wid >> 1;
    const int warp_m = wm * 64;
    const int warp_n = wn * 32;

    float acc[4][4][4];
#pragma unroll
    for (int i = 0; i < 4; i++)
#pragma unroll
        for (int j = 0; j < 4; j++)
#pragma unroll
            for (int k = 0; k < 4; k++) acc[i][j][k] = 0.0f;

    const int a_mo = (lane & 7) + ((lane >> 3) & 1) * 8;
    const int a_ko = ((lane >> 4) & 1) * 8;
    const int bl   = lane & 15;
    const int b_no = bl & 7;
    const int b_ko = ((bl >> 3) & 1) * 8;

    const int  b_row = tid & 127;
    const bool b_lo  = (tid >> 7) & 1;
    const __nv_bfloat16* bsrc = b_lo ? g_wlo : g_whi;

    float4 ra[4];
    uint4  rb[4];
#pragma unroll
    for (int i = 0; i < 4; i++) {
        int idx = tid + i * 256;
        int row = idx >> 3;
        int c4  = idx & 7;
        ra[i] = *reinterpret_cast<const float4*>(
            x + (size_t)(m0 + row) * NFEAT + c4 * 4);
    }
#pragma unroll
    for (int i = 0; i < 4; i++)
        rb[i] = *reinterpret_cast<const uint4*>(bsrc + b_row * NFEAT + i * 8);

    for (int k0 = 0; k0 < NFEAT; k0 += BK) {
        const int buf = (k0 >> 5) & 1;
#pragma unroll
        for (int i = 0; i < 4; i++) {
            int idx = tid + i * 256;
            int row = idx >> 3;
            int c4  = idx & 7;
            uint2 hi, lo;
            cvt_hilo(ra[i], hi, lo);
            *reinterpret_cast<uint2*>(&sAhi[buf][row * SAS + c4 * 4]) = hi;
            *reinterpret_cast<uint2*>(&sAlo[buf][row * SAS + c4 * 4]) = lo;
        }
        {
            __nv_bfloat16* bdst = b_lo ? sBlo[buf] : sBhi[buf];
#pragma unroll
            for (int i = 0; i < 4; i++)
                *reinterpret_cast<uint4*>(&bdst[b_row * SAS + i * 8]) = rb[i];
        }
        __syncthreads();

        if (k0 + BK < NFEAT) {
#pragma unroll
            for (int i = 0; i < 4; i++) {
                int idx = tid + i * 256;
                int row = idx >> 3;
                int c4  = idx & 7;
                ra[i] = *reinterpret_cast<const float4*>(
                    x + (size_t)(m0 + row) * NFEAT + (k0 + BK) + c4 * 4);
            }
#pragma unroll
            for (int i = 0; i < 4; i++)
                rb[i] = *reinterpret_cast<const uint4*>(
                    bsrc + b_row * NFEAT + (k0 + BK) + i * 8);
        }

#pragma unroll
        for (int ks = 0; ks < BK; ks += 16) {
            uint32_t ahi[4][4], alo[4][4], bhi[4][2], blo[4][2];
#pragma unroll
            for (int mi = 0; mi < 4; mi++) {
                int mrow = warp_m + mi * 16 + a_mo;
                int kcol = ks + a_ko;
                ldm_x4(smem_u32(&sAhi[buf][mrow * SAS + kcol]),
                       ahi[mi][0], ahi[mi][1], ahi[mi][2], ahi[mi][3]);
                ldm_x4(smem_u32(&sAlo[buf][mrow * SAS + kcol]),
                       alo[mi][0], alo[mi][1], alo[mi][2], alo[mi][3]);
            }
#pragma unroll
            for (int ni = 0; ni < 4; ni++) {
                int nrow = warp_n + ni * 8 + b_no;
                int kcol = ks + b_ko;
                ldm_x2(smem_u32(&sBhi[buf][nrow * SAS + kcol]), bhi[ni][0], bhi[ni][1]);
                ldm_x2(smem_u32(&sBlo[buf][nrow * SAS + kcol]), blo[ni][0], blo[ni][1]);
            }
#pragma unroll
            for (int mi = 0; mi < 4; mi++)
#pragma unroll
                for (int ni = 0; ni < 4; ni++) {
                    mma_bf16(acc[mi][ni], ahi[mi], bhi[ni]);
                    mma_bf16(acc[mi][ni], ahi[mi], blo[ni]);
                    mma_bf16(acc[mi][ni], alo[mi], bhi[ni]);
                }
        }
    }

    const int gid  = lane >> 2;
    const int tig  = lane & 3;
#pragma unroll
    for (int ni = 0; ni < 4; ni++) {
        int col = warp_n + ni * 8 + tig * 2;
        if (col < NGATE) {
            float bx = b_ih[col] + b_hh[col];
            float by = b_ih[col + 1] + b_hh[col + 1];
#pragma unroll
            for (int mi = 0; mi < 4; mi++) {
                int row = m0 + warp_m + mi * 16 + gid;
                float* c = acc[mi][ni];
                *reinterpret_cast<float2*>(&g_xg0[(size_t)row * NGATE + col]) =
                    make_float2(c[0] + bx, c[1] + by);
                *reinterpret_cast<float2*>(&g_xg0[(size_t)(row + 8) * NGATE + col]) =
                    make_float2(c[2] + bx, c[3] + by);
            }
        }
    }
}

// ---------------------------------------------------------------------------
// Kernel 2: fused 2-layer recurrent LSTM + final linear — balanced 3 roles.
// NB=8, 384 threads, 1 CTA/SM (reg ceiling 170 -> wp[30] fits, no spill),
// grid=128 -> single wave. Roles (equal 120-FFMA2 tasks, one warp of each
// per SMSP): warps 0-3 layer0 x 8 batches; warps 4-7 layer1 batches 0-3;
// warps 8-11 layer1 batches 4-7. One barrier per iteration; h double-buffered
// both batch-packed (layer0 reads) and {h0,h1}-interleaved (layer1 reads).
// ---------------------------------------------------------------------------
__device__ __forceinline__ float sig_raw(float x) {
    return __fdividef(1.0f, 1.0f + __expf(-x));
}
__device__ __forceinline__ float tanh_f(float x) {
    return fmaf(2.0f, sig_raw(2.0f * x), -1.0f);
}
// quad transpose: input v0..v3 = this lane's gate for batches 0..3;
// output (ti,tf,tg,to) = the 4 gate types of batch q (q = lane&3).
__device__ __forceinline__ void quad_transpose(int q, float v0, float v1,
                                               float v2, float v3,
                                               float& ti, float& tf,
                                               float& tg, float& to) {
    float s1 = (q & 1) ? v0 : v1;
    float r1s = __shfl_xor_sync(0xffffffffu, s1, 1);
    float s2 = (q & 1) ? v2 : v3;
    float r2s = __shfl_xor_sync(0xffffffffu, s2, 1);
    float u0 = (q & 1) ? r1s : v0;
    float u1 = (q & 1) ? v1 : r1s;
    float u2 = (q & 1) ? r2s : v2;
    float u3 = (q & 1) ? v3 : r2s;
    float s3 = (q & 2) ? u0 : u2;
    float r3s = __shfl_xor_sync(0xffffffffu, s3, 2);
    float s4 = (q & 2) ? u1 : u3;
    float r4s = __shfl_xor_sync(0xffffffffu, s4, 2);
    ti = (q & 2) ? r3s : u0;
    tf = (q & 2) ? r4s : u1;
    tg = (q & 2) ? u2 : r3s;
    to = (q & 2) ? u3 : r4s;
}

__global__ __launch_bounds__(384, 1) void lstm_rec(
    const float* __restrict__ w_hh0,
    const float* __restrict__ w_ih1,
    const float* __restrict__ w_hh1,
    const float* __restrict__ b_ih1,
    const float* __restrict__ b_hh1,
    const float* __restrict__ w_lin,
    const float* __restrict__ b_lin,
    float* __restrict__ out)
{
    const int b0   = blockIdx.x * NB;
    const int tid  = threadIdx.x;
    const int wid  = tid >> 5;
    const int lane = tid & 31;
    const int role = wid >> 2;              // 0: L0x8b, 1: L1 b0-3, 2: L1 b4-7
    const int wi   = wid & 3;
    const int j    = wi * 8 + (lane >> 2);
    const int q    = lane & 3;
    const bool jok = (j < NHID);
    const int jc   = jok ? j : (NHID - 1);
    const int gr   = q * 30 + jc;

    // layer0 h batch-packed: a = batches 0-3, b = batches 4-7
    __shared__ float4 sh_h0a[2][NHID];
    __shared__ float4 sh_h0b[2][NHID];
    // {h0,h1}-interleaved per batch pair: A={b0,b1} B={b2,b3} C={b4,b5} D={b6,b7}
    __shared__ float4 sh_hA[2][NHID];
    __shared__ float4 sh_hB[2][NHID];
    __shared__ float4 sh_hC[2][NHID];
    __shared__ float4 sh_hD[2][NHID];
    __shared__ float  sh_red[NB][32];

    // packed weights: role0 {w,w}; roles 1,2 {wA,wB}
    uint64_t wp[NHID];
    float bias1 = 0.0f;
    if (role == 0) {
#pragma unroll
        for (int k = 0; k < NHID; k++) {
            float w = w_hh0[gr * NHID + k];
            wp[k] = pack2(w, w);
        }
    } else {
#pragma unroll
        for (int k = 0; k < NHID; k++)
            wp[k] = pack2(w_ih1[gr * NHID + k], w_hh1[gr * NHID + k]);
        bias1 = b_ih1[gr] + b_hh1[gr];
    }

    float c_a = 0.0f, c_b = 0.0f;   // role0: batches q, q+4; roles1/2: c_a only
    float outacc = 0.0f;

    if (tid < NHID) {
        float4 z = make_float4(0.f, 0.f, 0.f, 0.f);
        sh_h0a[0][tid] = z; sh_h0a[1][tid] = z;
        sh_h0b[0][tid] = z; sh_h0b[1][tid] = z;
        sh_hA[0][tid] = z;  sh_hA[1][tid] = z;
        sh_hB[0][tid] = z;  sh_hB[1][tid] = z;
        sh_hC[0][tid] = z;  sh_hC[1][tid] = z;
        sh_hD[0][tid] = z;  sh_hD[1][tid] = z;
    }

    float xg_cur[NB];
    if (role == 0) {
#pragma unroll
        for (int bb = 0; bb < NB; bb++)
            xg_cur[bb] = __ldg(&g_xg0[((size_t)(b0 + bb) * SEQLEN) * NGATE + gr]);
    }
    __syncthreads();

    const float a_scale = (q == 2) ? 2.0f : 1.0f;
    const float a_mult  = (q == 2) ? 2.0f : 1.0f;
    const float a_add   = (q == 2) ? -1.0f : 0.0f;

    for (int p = 0; p <= SEQLEN; p++) {
        const int wb = p & 1;
        const int rb = wb ^ 1;
        const bool active = (role == 0) ? (p < SEQLEN) : (p >= 1);

        if (active) {
            if (role == 0) {
                uint64_t a01 = pack2(xg_cur[0], xg_cur[1]);
                uint64_t a23 = pack2(xg_cur[2], xg_cur[3]);
                uint64_t a45 = pack2(xg_cur[4], xg_cur[5]);
                uint64_t a67 = pack2(xg_cur[6], xg_cur[7]);
                if (p + 1 < SEQLEN) {
#pragma unroll
                    for (int bb = 0; bb < NB; bb++)
                        xg_cur[bb] = __ldg(&g_xg0[((size_t)(b0 + bb) * SEQLEN + p + 1) * NGATE + gr]);
                }
#pragma unroll
                for (int k = 0; k < NHID; k++) {
                    ulonglong2 ha = *reinterpret_cast<const ulonglong2*>(&sh_h0a[rb][k]);
                    ulonglong2 hb = *reinterpret_cast<const ulonglong2*>(&sh_h0b[rb][k]);
                    ffma2(a01, wp[k], ha.x);
                    ffma2(a23, wp[k], ha.y);
                    ffma2(a45, wp[k], hb.x);
                    ffma2(a67, wp[k], hb.y);
                }
                float2 p01 = unpack2(a01), p23 = unpack2(a23);
                float2 p45 = unpack2(a45), p67 = unpack2(a67);
                float v0 = fmaf(a_mult, sig_raw(p01.x * a_scale), a_add);
                float v1 = fmaf(a_mult, sig_raw(p01.y * a_scale), a_add);
                float v2 = fmaf(a_mult, sig_raw(p23.x * a_scale), a_add);
                float v3 = fmaf(a_mult, sig_raw(p23.y * a_scale), a_add);
                float v4 = fmaf(a_mult, sig_raw(p45.x * a_scale), a_add);
                float v5 = fmaf(a_mult, sig_raw(p45.y * a_scale), a_add);
                float v6 = fmaf(a_mult, sig_raw(p67.x * a_scale), a_add);
                float v7 = fmaf(a_mult, sig_raw(p67.y * a_scale), a_add);

                float ti, tf, tg, to;
                quad_transpose(q, v0, v1, v2, v3, ti, tf, tg, to);
                c_a = fmaf(tf, c_a, ti * tg);
                float hA_ = to * tanh_f(c_a);           // batch q
                quad_transpose(q, v4, v5, v6, v7, ti, tf, tg, to);
                c_b = fmaf(tf, c_b, ti * tg);
                float hB_ = to * tanh_f(c_b);           // batch q+4

                if (jok) {
                    ((float*)&sh_h0a[wb][j])[q] = hA_;
                    ((float*)&sh_h0b[wb][j])[q] = hB_;
                    float* pa = (q < 2) ? (float*)&sh_hA[wb][j] : (float*)&sh_hB[wb][j];
                    pa[(q & 1) * 2 + 0] = hA_;
                    float* pb = (q < 2) ? (float*)&sh_hC[wb][j] : (float*)&sh_hD[wb][j];
                    pb[(q & 1) * 2 + 0] = hB_;
                }
            } else {
                const float4* hX = (role == 1) ? sh_hA[rb] : sh_hC[rb];
                const float4* hY = (role == 1) ? sh_hB[rb] : sh_hD[rb];
                uint64_t a0 = pack2(bias1, 0.f);
                uint64_t a1 = a0, a2 = a0, a3 = a0;
                float wl = __ldg(&w_lin[(p - 1) * NHID + jc]);
#pragma unroll
                for (int k = 0; k < NHID; k++) {
                    ulonglong2 hx = *reinterpret_cast<const ulonglong2*>(&hX[k]);
                    ulonglong2 hy = *reinterpret_cast<const ulonglong2*>(&hY[k]);
                    ffma2(a0, wp[k], hx.x);
                    ffma2(a1, wp[k], hx.y);
                    ffma2(a2, wp[k], hy.x);
                    ffma2(a3, wp[k], hy.y);
                }
                float2 r0 = unpack2(a0), r1 = unpack2(a1);
                float2 r2 = unpack2(a2), r3 = unpack2(a3);
                float v0 = fmaf(a_mult, sig_raw((r0.x + r0.y) * a_scale), a_add);
                float v1 = fmaf(a_mult, sig_raw((r1.x + r1.y) * a_scale), a_add);
                float v2 = fmaf(a_mult, sig_raw((r2.x + r2.y) * a_scale), a_add);
                float v3 = fmaf(a_mult, sig_raw((r3.x + r3.y) * a_scale), a_add);

                float ti, tf, tg, to;
                quad_transpose(q, v0, v1, v2, v3, ti, tf, tg, to);
                c_a = fmaf(tf, c_a, ti * tg);
                float h = to * tanh_f(c_a);             // batch (role-1)*4 + q
                if (jok) {
                    float* pw = (role == 1)
                        ? ((q < 2) ? (float*)&sh_hA[wb][j] : (float*)&sh_hB[wb][j])
                        : ((q < 2) ? (float*)&sh_hC[wb][j] : (float*)&sh_hD[wb][j]);
                    pw[(q & 1) * 2 + 1] = h;
                    outacc = fmaf(h, wl, outacc);
                }
            }
        }
        __syncthreads();
    }

    // output reduction: role1 lane(q,j) holds batch q; role2 holds batch q+4
    if (role >= 1 && jok) sh_red[(role - 1) * 4 + q][j] = outacc;
    __syncthreads();
    if (tid < NB) {
        float s = b_lin[0];
#pragma unroll
        for (int jj = 0; jj < NHID; jj++) s += sh_red[tid][jj];
        out[b0 + tid] = s;
    }
}

// ---------------------------------------------------------------------------
// Entry point
// ---------------------------------------------------------------------------
extern "C" void kernel_launch(void* const* d_in, const int* in_sizes, int n_in,
                              void* d_out, int out_size)
{
    const float* x      = (const float*)d_in[0];
    const float* w_ih0  = (const float*)d_in[1];
    const float* w_hh0  = (const float*)d_in[2];
    const float* b_ih0  = (const float*)d_in[3];
    const float* b_hh0  = (const float*)d_in[4];
    const float* w_ih1  = (const float*)d_in[5];
    const float* w_hh1  = (const float*)d_in[6];
    const float* b_ih1  = (const float*)d_in[7];
    const float* b_hh1  = (const float*)d_in[8];
    const float* w_lin  = (const float*)d_in[9];
    const float* b_lin  = (const float*)d_in[10];
    float* out = (float*)d_out;

    wcvt<<<32, 256>>>(w_ih0);
    gemm_xg0_tc<<<MROWS / 128, 256>>>(x, b_ih0, b_hh0);
    lstm_rec<<<BATCH / NB, 384>>>(w_hh0, w_ih1, w_hh1, b_ih1, b_hh1, w_lin, b_lin, out);
}

// round 16
// speedup vs baseline: 1.1560x; 1.1560x over previous
#include <cuda_runtime.h>
#include <cuda_bf16.h>
#include <cstdint>

// Problem constants
#define BATCH   1024
#define SEQLEN  128
#define NFEAT   256
#define NHID    30
#define NGATE   120          // 4*NHID
#define MROWS   (BATCH*SEQLEN)   // 131072
#define NB      4            // batch elements per recurrent CTA

__device__ float g_xg0[(size_t)MROWS * NGATE];

// ---------------------------------------------------------------------------
// packed f32x2 helpers (sm_103a FFMA2 — only reachable via PTX)
// ---------------------------------------------------------------------------
__device__ __forceinline__ void ffma2(uint64_t& d, uint64_t a, uint64_t b) {
    asm("fma.rn.f32x2 %0, %1, %2, %0;" : "+l"(d) : "l"(a), "l"(b));
}
__device__ __forceinline__ uint64_t pack2(float lo, float hi) {
    uint64_t r;
    asm("mov.b64 %0, {%1,%2};" : "=l"(r) : "f"(lo), "f"(hi));
    return r;
}
__device__ __forceinline__ float2 unpack2(uint64_t v) {
    float2 r;
    asm("mov.b64 {%0,%1}, %2;" : "=f"(r.x), "=f"(r.y) : "l"(v));
    return r;
}

// ---------------------------------------------------------------------------
// Kernel 1: xg0 = x @ w_ih0^T + bias -- split-bf16 tensor core, double-buffered
// B split-conversion is done INLINE (wcvt kernel eliminated): B is prefetched
// raw fp32 with the same 256x4-float4 mapping as A, so prefetch register
// footprint is unchanged vs the verified round-10 config.
// ---------------------------------------------------------------------------
#define BK     32
#define SAS    40

__device__ __forceinline__ uint32_t smem_u32(const void* p) {
    return (uint32_t)__cvta_generic_to_shared(p);
}
__device__ __forceinline__ void ldm_x4(uint32_t addr, uint32_t& r0, uint32_t& r1,
                                       uint32_t& r2, uint32_t& r3) {
    asm volatile("ldmatrix.sync.aligned.m8n8.x4.shared.b16 {%0,%1,%2,%3}, [%4];"
                 : "=r"(r0), "=r"(r1), "=r"(r2), "=r"(r3) : "r"(addr));
}
__device__ __forceinline__ void ldm_x2(uint32_t addr, uint32_t& r0, uint32_t& r1) {
    asm volatile("ldmatrix.sync.aligned.m8n8.x2.shared.b16 {%0,%1}, [%2];"
                 : "=r"(r0), "=r"(r1) : "r"(addr));
}
__device__ __forceinline__ void mma_bf16(float* c, const uint32_t* a, const uint32_t* b) {
    asm volatile(
        "mma.sync.aligned.m16n8k16.row.col.f32.bf16.bf16.f32 "
        "{%0,%1,%2,%3}, {%4,%5,%6,%7}, {%8,%9}, {%0,%1,%2,%3};"
        : "+f"(c[0]), "+f"(c[1]), "+f"(c[2]), "+f"(c[3])
        : "r"(a[0]), "r"(a[1]), "r"(a[2]), "r"(a[3]), "r"(b[0]), "r"(b[1]));
}
__device__ __forceinline__ void cvt_hilo(float4 v, uint2& hi, uint2& lo) {
    uint32_t bx = __float_as_uint(v.x), by = __float_as_uint(v.y);
    uint32_t bz = __float_as_uint(v.z), bw = __float_as_uint(v.w);
    hi.x = __byte_perm(bx, by, 0x7632);
    hi.y = __byte_perm(bz, bw, 0x7632);
    float lx = v.x - __uint_as_float(bx & 0xffff0000u);
    float ly = v.y - __uint_as_float(by & 0xffff0000u);
    float lz = v.z - __uint_as_float(bz & 0xffff0000u);
    float lw = v.w - __uint_as_float(bw & 0xffff0000u);
    __nv_bfloat162 l01 = __floats2bfloat162_rn(lx, ly);
    __nv_bfloat162 l23 = __floats2bfloat162_rn(lz, lw);
    lo.x = *reinterpret_cast<uint32_t*>(&l01);
    lo.y = *reinterpret_cast<uint32_t*>(&l23);
}

__global__ __launch_bounds__(256, 2) void gemm_xg0_tc(
    const float* __restrict__ x,
    const float* __restrict__ w,      // [120,256] raw fp32
    const float* __restrict__ b_ih,
    const float* __restrict__ b_hh)
{
    __shared__ __nv_bfloat16 sAhi[2][128 * SAS];
    __shared__ __nv_bfloat16 sAlo[2][128 * SAS];
    __shared__ __nv_bfloat16 sBhi[2][128 * SAS];
    __shared__ __nv_bfloat16 sBlo[2][128 * SAS];

    const int tid  = threadIdx.x;
    const int lane = tid & 31;
    const int wid  = tid >> 5;
    const int m0   = blockIdx.x * 128;

    const int wm = wid & 1;
    const int wn = wid >> 1;
    const int warp_m = wm * 64;
    const int warp_n = wn * 32;

    float acc[4][4][4];
#pragma unroll
    for (int i = 0; i < 4; i++)
#pragma unroll
        for (int j = 0; j < 4; j++)
#pragma unroll
            for (int k = 0; k < 4; k++) acc[i][j][k] = 0.0f;

    const int a_mo = (lane & 7) + ((lane >> 3) & 1) * 8;
    const int a_ko = ((lane >> 4) & 1) * 8;
    const int bl   = lane & 15;
    const int b_no = bl & 7;
    const int b_ko = ((bl >> 3) & 1) * 8;

    // prologue: prefetch chunk 0 into registers (A rows of x, B rows of w)
    float4 ra[4], rbf[4];
#pragma unroll
    for (int i = 0; i < 4; i++) {
        int idx = tid + i * 256;
        int row = idx >> 3;
        int c4  = idx & 7;
        ra[i] = *reinterpret_cast<const float4*>(
            x + (size_t)(m0 + row) * NFEAT + c4 * 4);
        rbf[i] = make_float4(0.f, 0.f, 0.f, 0.f);
        if (row < NGATE)
            rbf[i] = *reinterpret_cast<const float4*>(
                w + (size_t)row * NFEAT + c4 * 4);
    }

    for (int k0 = 0; k0 < NFEAT; k0 += BK) {
        const int buf = (k0 >> 5) & 1;
        // ---- store prefetched chunk into ping-pong buffer (both converted)
#pragma unroll
        for (int i = 0; i < 4; i++) {
            int idx = tid + i * 256;
            int row = idx >> 3;
            int c4  = idx & 7;
            uint2 hi, lo;
            cvt_hilo(ra[i], hi, lo);
            *reinterpret_cast<uint2*>(&sAhi[buf][row * SAS + c4 * 4]) = hi;
            *reinterpret_cast<uint2*>(&sAlo[buf][row * SAS + c4 * 4]) = lo;
            cvt_hilo(rbf[i], hi, lo);
            *reinterpret_cast<uint2*>(&sBhi[buf][row * SAS + c4 * 4]) = hi;
            *reinterpret_cast<uint2*>(&sBlo[buf][row * SAS + c4 * 4]) = lo;
        }
        __syncthreads();   // the ONLY barrier per chunk

        // ---- prefetch next chunk (LDG latency hides under mma below)
        if (k0 + BK < NFEAT) {
#pragma unroll
            for (int i = 0; i < 4; i++) {
                int idx = tid + i * 256;
                int row = idx >> 3;
                int c4  = idx & 7;
                ra[i] = *reinterpret_cast<const float4*>(
                    x + (size_t)(m0 + row) * NFEAT + (k0 + BK) + c4 * 4);
                if (row < NGATE)
                    rbf[i] = *reinterpret_cast<const float4*>(
                        w + (size_t)row * NFEAT + (k0 + BK) + c4 * 4);
            }
        }

        // ---- mma over this buffer
#pragma unroll
        for (int ks = 0; ks < BK; ks += 16) {
            uint32_t ahi[4][4], alo[4][4], bhi[4][2], blo[4][2];
#pragma unroll
            for (int mi = 0; mi < 4; mi++) {
                int mrow = warp_m + mi * 16 + a_mo;
                int kcol = ks + a_ko;
                ldm_x4(smem_u32(&sAhi[buf][mrow * SAS + kcol]),
                       ahi[mi][0], ahi[mi][1], ahi[mi][2], ahi[mi][3]);
                ldm_x4(smem_u32(&sAlo[buf][mrow * SAS + kcol]),
                       alo[mi][0], alo[mi][1], alo[mi][2], alo[mi][3]);
            }
#pragma unroll
            for (int ni = 0; ni < 4; ni++) {
                int nrow = warp_n + ni * 8 + b_no;
                int kcol = ks + b_ko;
                ldm_x2(smem_u32(&sBhi[buf][nrow * SAS + kcol]), bhi[ni][0], bhi[ni][1]);
                ldm_x2(smem_u32(&sBlo[buf][nrow * SAS + kcol]), blo[ni][0], blo[ni][1]);
            }
#pragma unroll
            for (int mi = 0; mi < 4; mi++)
#pragma unroll
                for (int ni = 0; ni < 4; ni++) {
                    mma_bf16(acc[mi][ni], ahi[mi], bhi[ni]);
                    mma_bf16(acc[mi][ni], ahi[mi], blo[ni]);
                    mma_bf16(acc[mi][ni], alo[mi], bhi[ni]);
                }
        }
        // no trailing barrier: next iteration writes the other buffer
    }

    const int gid  = lane >> 2;
    const int tig  = lane & 3;
#pragma unroll
    for (int ni = 0; ni < 4; ni++) {
        int col = warp_n + ni * 8 + tig * 2;
        if (col < NGATE) {
            float bx = b_ih[col] + b_hh[col];
            float by = b_ih[col + 1] + b_hh[col + 1];
#pragma unroll
            for (int mi = 0; mi < 4; mi++) {
                int row = m0 + warp_m + mi * 16 + gid;
                float* c = acc[mi][ni];
                *reinterpret_cast<float2*>(&g_xg0[(size_t)row * NGATE + col]) =
                    make_float2(c[0] + bx, c[1] + by);
                *reinterpret_cast<float2*>(&g_xg0[(size_t)(row + 8) * NGATE + col]) =
                    make_float2(c[2] + bx, c[3] + by);
            }
        }
    }
}

// ---------------------------------------------------------------------------
// Kernel 2: fused 2-layer recurrent LSTM + final linear — FFMA2 edition.
// (round-8 verified: 140us; byte-identical)
// ---------------------------------------------------------------------------
__device__ __forceinline__ float sig_raw(float x) {
    return __fdividef(1.0f, 1.0f + __expf(-x));
}
__device__ __forceinline__ float tanh_f(float x) {
    return fmaf(2.0f, sig_raw(2.0f * x), -1.0f);
}

__global__ __launch_bounds__(256, 2) void lstm_rec(
    const float* __restrict__ w_hh0,
    const float* __restrict__ w_ih1,
    const float* __restrict__ w_hh1,
    const float* __restrict__ b_ih1,
    const float* __restrict__ b_hh1,
    const float* __restrict__ w_lin,
    const float* __restrict__ b_lin,
    float* __restrict__ out)
{
    const int b0   = blockIdx.x * NB;
    const int tid  = threadIdx.x;
    const int wid  = tid >> 5;
    const int lane = tid & 31;
    const int layer = wid >> 2;
    const int wi    = wid & 3;
    const int j     = wi * 8 + (lane >> 2);
    const int q     = lane & 3;
    const bool jok  = (j < NHID);
    const int jc    = jok ? j : (NHID - 1);
    const int gr    = q * 30 + jc;

    __shared__ float4 sh_h0p[2][NHID];
    __shared__ float4 sh_hA[2][NHID];
    __shared__ float4 sh_hB[2][NHID];
    __shared__ float  sh_red[NB][32];

    uint64_t wp[NHID];
    float bias1 = 0.0f;
    if (layer == 0) {
#pragma unroll
        for (int k = 0; k < NHID; k++) {
            float w = w_hh0[gr * NHID + k];
            wp[k] = pack2(w, w);
        }
    } else {
#pragma unroll
        for (int k = 0; k < NHID; k++)
            wp[k] = pack2(w_ih1[gr * NHID + k], w_hh1[gr * NHID + k]);
        bias1 = b_ih1[gr] + b_hh1[gr];
    }

    float c = 0.0f, outacc = 0.0f;

    if (tid < NHID) {
        float4 z = make_float4(0.f, 0.f, 0.f, 0.f);
        sh_h0p[0][tid] = z; sh_h0p[1][tid] = z;
        sh_hA[0][tid]  = z; sh_hA[1][tid]  = z;
        sh_hB[0][tid]  = z; sh_hB[1][tid]  = z;
    }

    float xg_cur[NB];
    if (layer == 0) {
#pragma unroll
        for (int bb = 0; bb < NB; bb++)
            xg_cur[bb] = __ldg(&g_xg0[((size_t)(b0 + bb) * SEQLEN) * NGATE + gr]);
    }
    __syncthreads();

    const float a_scale = (q == 2) ? 2.0f : 1.0f;
    const float a_mult  = (q == 2) ? 2.0f : 1.0f;
    const float a_add   = (q == 2) ? -1.0f : 0.0f;

    for (int p = 0; p <= SEQLEN; p++) {
        const int wb = p & 1;
        const int rb = wb ^ 1;
        const bool active = (layer == 0) ? (p < SEQLEN) : (p >= 1);

        if (active) {
            float v0, v1, v2, v3;
            float wl = 0.0f;
            if (layer == 0) {
                uint64_t a01 = pack2(xg_cur[0], xg_cur[1]);
                uint64_t a23 = pack2(xg_cur[2], xg_cur[3]);
                if (p + 1 < SEQLEN) {
#pragma unroll
                    for (int bb = 0; bb < NB; bb++)
                        xg_cur[bb] = __ldg(&g_xg0[((size_t)(b0 + bb) * SEQLEN + p + 1) * NGATE + gr]);
                }
#pragma unroll
                for (int k = 0; k < NHID; k++) {
                    ulonglong2 h = *reinterpret_cast<const ulonglong2*>(&sh_h0p[rb][k]);
                    ffma2(a01, wp[k], h.x);
                    ffma2(a23, wp[k], h.y);
                }
                float2 p01 = unpack2(a01), p23 = unpack2(a23);
                v0 = p01.x; v1 = p01.y; v2 = p23.x; v3 = p23.y;
            } else {
                uint64_t a0 = pack2(bias1, 0.f);
                uint64_t a1 = a0, a2 = a0, a3 = a0;
                wl = __ldg(&w_lin[(p - 1) * NHID + jc]);
#pragma unroll
                for (int k = 0; k < NHID; k++) {
                    ulonglong2 hA = *reinterpret_cast<const ulonglong2*>(&sh_hA[rb][k]);
                    ulonglong2 hB = *reinterpret_cast<const ulonglong2*>(&sh_hB[rb][k]);
                    ffma2(a0, wp[k], hA.x);
                    ffma2(a1, wp[k], hA.y);
                    ffma2(a2, wp[k], hB.x);
                    ffma2(a3, wp[k], hB.y);
                }
                float2 r0 = unpack2(a0), r1 = unpack2(a1);
                float2 r2 = unpack2(a2), r3 = unpack2(a3);
                v0 = r0.x + r0.y; v1 = r1.x + r1.y;
                v2 = r2.x + r2.y; v3 = r3.x + r3.y;
            }
            v0 = fmaf(a_mult, sig_raw(v0 * a_scale), a_add);
            v1 = fmaf(a_mult, sig_raw(v1 * a_scale), a_add);
            v2 = fmaf(a_mult, sig_raw(v2 * a_scale), a_add);
            v3 = fmaf(a_mult, sig_raw(v3 * a_scale), a_add);

            float s1 = (q & 1) ? v0 : v1;
            float r1s = __shfl_xor_sync(0xffffffffu, s1, 1);
            float s2 = (q & 1) ? v2 : v3;
            float r2s = __shfl_xor_sync(0xffffffffu, s2, 1);
            float u0 = (q & 1) ? r1s : v0;
            float u1 = (q & 1) ? v1 : r1s;
            float u2 = (q & 1) ? r2s : v2;
            float u3 = (q & 1) ? v3 : r2s;
            float s3 = (q & 2) ? u0 : u2;
            float r3s = __shfl_xor_sync(0xffffffffu, s3, 2);
            float s4 = (q & 2) ? u1 : u3;
            float r4s = __shfl_xor_sync(0xffffffffu, s4, 2);
            float ti = (q & 2) ? r3s : u0;
            float tf = (q & 2) ? r4s : u1;
            float tg = (q & 2) ? u2 : r3s;
            float to = (q & 2) ? u3 : r4s;

            c = fmaf(tf, c, ti * tg);
            float h = to * tanh_f(c);
            if (jok) {
                float* pb = (q < 2) ? (float*)&sh_hA[wb][j] : (float*)&sh_hB[wb][j];
                pb[(q & 1) * 2 + layer] = h;
                if (layer == 0) {
                    ((float*)&sh_h0p[wb][j])[q] = h;
                } else {
                    outacc = fmaf(h, wl, outacc);
                }
            }
        }
        __syncthreads();
    }

    if (layer == 1 && jok) sh_red[q][j] = outacc;
    __syncthreads();
    if (tid < NB) {
        float s = b_lin[0];
#pragma unroll
        for (int jj = 0; jj < NHID; jj++) s += sh_red[tid][jj];
        out[b0 + tid] = s;
    }
}

// ---------------------------------------------------------------------------
// Entry point: two launches only (wcvt folded into the GEMM)
// ---------------------------------------------------------------------------
extern "C" void kernel_launch(void* const* d_in, const int* in_sizes, int n_in,
                              void* d_out, int out_size)
{
    const float* x      = (const float*)d_in[0];
    const float* w_ih0  = (const float*)d_in[1];
    const float* w_hh0  = (const float*)d_in[2];
    const float* b_ih0  = (const float*)d_in[3];
    const float* b_hh0  = (const float*)d_in[4];
    const float* w_ih1  = (const float*)d_in[5];
    const float* w_hh1  = (const float*)d_in[6];
    const float* b_ih1  = (const float*)d_in[7];
    const float* b_hh1  = (const float*)d_in[8];
    const float* w_lin  = (const float*)d_in[9];
    const float* b_lin  = (const float*)d_in[10];
    float* out = (float*)d_out;

    gemm_xg0_tc<<<MROWS / 128, 256>>>(x, w_ih0, b_ih0, b_hh0);
    lstm_rec<<<BATCH / NB, 256>>>(w_hh0, w_ih1, w_hh1, b_ih1, b_hh1, w_lin, b_lin, out);
}

// round 17
// speedup vs baseline: 1.1638x; 1.0068x over previous
#include <cuda_runtime.h>
#include <cuda_bf16.h>
#include <cstdint>

// Problem constants
#define BATCH   1024
#define SEQLEN  128
#define NFEAT   256
#define NHID    30
#define NGATE   120          // 4*NHID
#define MROWS   (BATCH*SEQLEN)   // 131072
#define NB      4            // batch elements per recurrent CTA

__device__ float g_xg0[(size_t)MROWS * NGATE];

// ---------------------------------------------------------------------------
// packed f32x2 helpers (sm_103a FFMA2 — only reachable via PTX)
// ---------------------------------------------------------------------------
__device__ __forceinline__ void ffma2(uint64_t& d, uint64_t a, uint64_t b) {
    asm("fma.rn.f32x2 %0, %1, %2, %0;" : "+l"(d) : "l"(a), "l"(b));
}
__device__ __forceinline__ uint64_t pack2(float lo, float hi) {
    uint64_t r;
    asm("mov.b64 %0, {%1,%2};" : "=l"(r) : "f"(lo), "f"(hi));
    return r;
}
__device__ __forceinline__ float2 unpack2(uint64_t v) {
    float2 r;
    asm("mov.b64 {%0,%1}, %2;" : "=f"(r.x), "=f"(r.y) : "l"(v));
    return r;
}

// ---------------------------------------------------------------------------
// Kernel 1: xg0 = x @ w_ih0^T + bias -- split-bf16 tensor core, double-buffered
// Conversion is done AT PREFETCH TIME (in the mma phase's issue slack, under
// the LDG latency already being hidden), so the pre-barrier phase is pure
// STS.64. Prefetch buffers are packed hi/lo uint2 (half the registers of the
// raw-fp32 variant). Arithmetic bit-identical to round 16.
// ---------------------------------------------------------------------------
#define BK     32
#define SAS    40

__device__ __forceinline__ uint32_t smem_u32(const void* p) {
    return (uint32_t)__cvta_generic_to_shared(p);
}
__device__ __forceinline__ void ldm_x4(uint32_t addr, uint32_t& r0, uint32_t& r1,
                                       uint32_t& r2, uint32_t& r3) {
    asm volatile("ldmatrix.sync.aligned.m8n8.x4.shared.b16 {%0,%1,%2,%3}, [%4];"
                 : "=r"(r0), "=r"(r1), "=r"(r2), "=r"(r3) : "r"(addr));
}
__device__ __forceinline__ void ldm_x2(uint32_t addr, uint32_t& r0, uint32_t& r1) {
    asm volatile("ldmatrix.sync.aligned.m8n8.x2.shared.b16 {%0,%1}, [%2];"
                 : "=r"(r0), "=r"(r1) : "r"(addr));
}
__device__ __forceinline__ void mma_bf16(float* c, const uint32_t* a, const uint32_t* b) {
    asm volatile(
        "mma.sync.aligned.m16n8k16.row.col.f32.bf16.bf16.f32 "
        "{%0,%1,%2,%3}, {%4,%5,%6,%7}, {%8,%9}, {%0,%1,%2,%3};"
        : "+f"(c[0]), "+f"(c[1]), "+f"(c[2]), "+f"(c[3])
        : "r"(a[0]), "r"(a[1]), "r"(a[2]), "r"(a[3]), "r"(b[0]), "r"(b[1]));
}
__device__ __forceinline__ void cvt_hilo(float4 v, uint2& hi, uint2& lo) {
    uint32_t bx = __float_as_uint(v.x), by = __float_as_uint(v.y);
    uint32_t bz = __float_as_uint(v.z), bw = __float_as_uint(v.w);
    hi.x = __byte_perm(bx, by, 0x7632);
    hi.y = __byte_perm(bz, bw, 0x7632);
    float lx = v.x - __uint_as_float(bx & 0xffff0000u);
    float ly = v.y - __uint_as_float(by & 0xffff0000u);
    float lz = v.z - __uint_as_float(bz & 0xffff0000u);
    float lw = v.w - __uint_as_float(bw & 0xffff0000u);
    __nv_bfloat162 l01 = __floats2bfloat162_rn(lx, ly);
    __nv_bfloat162 l23 = __floats2bfloat162_rn(lz, lw);
    lo.x = *reinterpret_cast<uint32_t*>(&l01);
    lo.y = *reinterpret_cast<uint32_t*>(&l23);
}

__global__ __launch_bounds__(256, 2) void gemm_xg0_tc(
    const float* __restrict__ x,
    const float* __restrict__ w,      // [120,256] raw fp32
    const float* __restrict__ b_ih,
    const float* __restrict__ b_hh)
{
    __shared__ __nv_bfloat16 sAhi[2][128 * SAS];
    __shared__ __nv_bfloat16 sAlo[2][128 * SAS];
    __shared__ __nv_bfloat16 sBhi[2][128 * SAS];
    __shared__ __nv_bfloat16 sBlo[2][128 * SAS];

    const int tid  = threadIdx.x;
    const int lane = tid & 31;
    const int wid  = tid >> 5;
    const int m0   = blockIdx.x * 128;

    const int wm = wid & 1;
    const int wn = wid >> 1;
    const int warp_m = wm * 64;
    const int warp_n = wn * 32;

    float acc[4][4][4];
#pragma unroll
    for (int i = 0; i < 4; i++)
#pragma unroll
        for (int j = 0; j < 4; j++)
#pragma unroll
            for (int k = 0; k < 4; k++) acc[i][j][k] = 0.0f;

    const int a_mo = (lane & 7) + ((lane >> 3) & 1) * 8;
    const int a_ko = ((lane >> 4) & 1) * 8;
    const int bl   = lane & 15;
    const int b_no = bl & 7;
    const int b_ko = ((bl >> 3) & 1) * 8;

    // Per-thread fill coordinates (same 256x4-float4 mapping for A and B)
    const int f_row[1] = {0};  // placeholder to keep structure readable
    (void)f_row;

    // prologue: prefetch chunk 0 and convert immediately; only packed hi/lo
    // uint2 stay live (32 regs total for A+B instead of 64 raw fp32)
    uint2 rahi[4], ralo[4], rbhi[4], rblo[4];
#pragma unroll
    for (int i = 0; i < 4; i++) {
        int idx = tid + i * 256;
        int row = idx >> 3;
        int c4  = idx & 7;
        float4 v = *reinterpret_cast<const float4*>(
            x + (size_t)(m0 + row) * NFEAT + c4 * 4);
        cvt_hilo(v, rahi[i], ralo[i]);
        float4 wv = make_float4(0.f, 0.f, 0.f, 0.f);
        if (row < NGATE)
            wv = *reinterpret_cast<const float4*>(
                w + (size_t)row * NFEAT + c4 * 4);
        cvt_hilo(wv, rbhi[i], rblo[i]);
    }

    for (int k0 = 0; k0 < NFEAT; k0 += BK) {
        const int buf = (k0 >> 5) & 1;
        // ---- store phase: pure STS.64 (conversion already done)
#pragma unroll
        for (int i = 0; i < 4; i++) {
            int idx = tid + i * 256;
            int row = idx >> 3;
            int c4  = idx & 7;
            *reinterpret_cast<uint2*>(&sAhi[buf][row * SAS + c4 * 4]) = rahi[i];
            *reinterpret_cast<uint2*>(&sAlo[buf][row * SAS + c4 * 4]) = ralo[i];
            *reinterpret_cast<uint2*>(&sBhi[buf][row * SAS + c4 * 4]) = rbhi[i];
            *reinterpret_cast<uint2*>(&sBlo[buf][row * SAS + c4 * 4]) = rblo[i];
        }
        __syncthreads();   // the ONLY barrier per chunk

        // ---- prefetch + convert next chunk (hides under mma below)
        if (k0 + BK < NFEAT) {
#pragma unroll
            for (int i = 0; i < 4; i++) {
                int idx = tid + i * 256;
                int row = idx >> 3;
                int c4  = idx & 7;
                float4 v = *reinterpret_cast<const float4*>(
                    x + (size_t)(m0 + row) * NFEAT + (k0 + BK) + c4 * 4);
                cvt_hilo(v, rahi[i], ralo[i]);
                float4 wv = make_float4(0.f, 0.f, 0.f, 0.f);
                if (row < NGATE)
                    wv = *reinterpret_cast<const float4*>(
                        w + (size_t)row * NFEAT + (k0 + BK) + c4 * 4);
                cvt_hilo(wv, rbhi[i], rblo[i]);
            }
        }

        // ---- mma over this buffer
#pragma unroll
        for (int ks = 0; ks < BK; ks += 16) {
            uint32_t ahi[4][4], alo[4][4], bhi[4][2], blo[4][2];
#pragma unroll
            for (int mi = 0; mi < 4; mi++) {
                int mrow = warp_m + mi * 16 + a_mo;
                int kcol = ks + a_ko;
                ldm_x4(smem_u32(&sAhi[buf][mrow * SAS + kcol]),
                       ahi[mi][0], ahi[mi][1], ahi[mi][2], ahi[mi][3]);
                ldm_x4(smem_u32(&sAlo[buf][mrow * SAS + kcol]),
                       alo[mi][0], alo[mi][1], alo[mi][2], alo[mi][3]);
            }
#pragma unroll
            for (int ni = 0; ni < 4; ni++) {
                int nrow = warp_n + ni * 8 + b_no;
                int kcol = ks + b_ko;
                ldm_x2(smem_u32(&sBhi[buf][nrow * SAS + kcol]), bhi[ni][0], bhi[ni][1]);
                ldm_x2(smem_u32(&sBlo[buf][nrow * SAS + kcol]), blo[ni][0], blo[ni][1]);
            }
#pragma unroll
            for (int mi = 0; mi < 4; mi++)
#pragma unroll
                for (int ni = 0; ni < 4; ni++) {
                    mma_bf16(acc[mi][ni], ahi[mi], bhi[ni]);
                    mma_bf16(acc[mi][ni], ahi[mi], blo[ni]);
                    mma_bf16(acc[mi][ni], alo[mi], bhi[ni]);
                }
        }
        // no trailing barrier: next iteration writes the other buffer
    }

    const int gid  = lane >> 2;
    const int tig  = lane & 3;
#pragma unroll
    for (int ni = 0; ni < 4; ni++) {
        int col = warp_n + ni * 8 + tig * 2;
        if (col < NGATE) {
            float bx = b_ih[col] + b_hh[col];
            float by = b_ih[col + 1] + b_hh[col + 1];
#pragma unroll
            for (int mi = 0; mi < 4; mi++) {
                int row = m0 + warp_m + mi * 16 + gid;
                float* c = acc[mi][ni];
                *reinterpret_cast<float2*>(&g_xg0[(size_t)row * NGATE + col]) =
                    make_float2(c[0] + bx, c[1] + by);
                *reinterpret_cast<float2*>(&g_xg0[(size_t)(row + 8) * NGATE + col]) =
                    make_float2(c[2] + bx, c[3] + by);
            }
        }
    }
}

// ---------------------------------------------------------------------------
// Kernel 2: fused 2-layer recurrent LSTM + final linear — FFMA2 edition.
// (round-8 verified: ~141us; byte-identical)
// ---------------------------------------------------------------------------
__device__ __forceinline__ float sig_raw(float x) {
    return __fdividef(1.0f, 1.0f + __expf(-x));
}
__device__ __forceinline__ float tanh_f(float x) {
    return fmaf(2.0f, sig_raw(2.0f * x), -1.0f);
}

__global__ __launch_bounds__(256, 2) void lstm_rec(
    const float* __restrict__ w_hh0,
    const float* __restrict__ w_ih1,
    const float* __restrict__ w_hh1,
    const float* __restrict__ b_ih1,
    const float* __restrict__ b_hh1,
    const float* __restrict__ w_lin,
    const float* __restrict__ b_lin,
    float* __restrict__ out)
{
    const int b0   = blockIdx.x * NB;
    const int tid  = threadIdx.x;
    const int wid  = tid >> 5;
    const int lane = tid & 31;
    const int layer = wid >> 2;
    const int wi    = wid & 3;
    const int j     = wi * 8 + (lane >> 2);
    const int q     = lane & 3;
    const bool jok  = (j < NHID);
    const int jc    = jok ? j : (NHID - 1);
    const int gr    = q * 30 + jc;

    __shared__ float4 sh_h0p[2][NHID];
    __shared__ float4 sh_hA[2][NHID];
    __shared__ float4 sh_hB[2][NHID];
    __shared__ float  sh_red[NB][32];

    uint64_t wp[NHID];
    float bias1 = 0.0f;
    if (layer == 0) {
#pragma unroll
        for (int k = 0; k < NHID; k++) {
            float w = w_hh0[gr * NHID + k];
            wp[k] = pack2(w, w);
        }
    } else {
#pragma unroll
        for (int k = 0; k < NHID; k++)
            wp[k] = pack2(w_ih1[gr * NHID + k], w_hh1[gr * NHID + k]);
        bias1 = b_ih1[gr] + b_hh1[gr];
    }

    float c = 0.0f, outacc = 0.0f;

    if (tid < NHID) {
        float4 z = make_float4(0.f, 0.f, 0.f, 0.f);
        sh_h0p[0][tid] = z; sh_h0p[1][tid] = z;
        sh_hA[0][tid]  = z; sh_hA[1][tid]  = z;
        sh_hB[0][tid]  = z; sh_hB[1][tid]  = z;
    }

    float xg_cur[NB];
    if (layer == 0) {
#pragma unroll
        for (int bb = 0; bb < NB; bb++)
            xg_cur[bb] = __ldg(&g_xg0[((size_t)(b0 + bb) * SEQLEN) * NGATE + gr]);
    }
    __syncthreads();

    const float a_scale = (q == 2) ? 2.0f : 1.0f;
    const float a_mult  = (q == 2) ? 2.0f : 1.0f;
    const float a_add   = (q == 2) ? -1.0f : 0.0f;

    for (int p = 0; p <= SEQLEN; p++) {
        const int wb = p & 1;
        const int rb = wb ^ 1;
        const bool active = (layer == 0) ? (p < SEQLEN) : (p >= 1);

        if (active) {
            float v0, v1, v2, v3;
            float wl = 0.0f;
            if (layer == 0) {
                uint64_t a01 = pack2(xg_cur[0], xg_cur[1]);
                uint64_t a23 = pack2(xg_cur[2], xg_cur[3]);
                if (p + 1 < SEQLEN) {
#pragma unroll
                    for (int bb = 0; bb < NB; bb++)
                        xg_cur[bb] = __ldg(&g_xg0[((size_t)(b0 + bb) * SEQLEN + p + 1) * NGATE + gr]);
                }
#pragma unroll
                for (int k = 0; k < NHID; k++) {
                    ulonglong2 h = *reinterpret_cast<const ulonglong2*>(&sh_h0p[rb][k]);
                    ffma2(a01, wp[k], h.x);
                    ffma2(a23, wp[k], h.y);
                }
                float2 p01 = unpack2(a01), p23 = unpack2(a23);
                v0 = p01.x; v1 = p01.y; v2 = p23.x; v3 = p23.y;
            } else {
                uint64_t a0 = pack2(bias1, 0.f);
                uint64_t a1 = a0, a2 = a0, a3 = a0;
                wl = __ldg(&w_lin[(p - 1) * NHID + jc]);
#pragma unroll
                for (int k = 0; k < NHID; k++) {
                    ulonglong2 hA = *reinterpret_cast<const ulonglong2*>(&sh_hA[rb][k]);
                    ulonglong2 hB = *reinterpret_cast<const ulonglong2*>(&sh_hB[rb][k]);
                    ffma2(a0, wp[k], hA.x);
                    ffma2(a1, wp[k], hA.y);
                    ffma2(a2, wp[k], hB.x);
                    ffma2(a3, wp[k], hB.y);
                }
                float2 r0 = unpack2(a0), r1 = unpack2(a1);
                float2 r2 = unpack2(a2), r3 = unpack2(a3);
                v0 = r0.x + r0.y; v1 = r1.x + r1.y;
                v2 = r2.x + r2.y; v3 = r3.x + r3.y;
            }
            v0 = fmaf(a_mult, sig_raw(v0 * a_scale), a_add);
            v1 = fmaf(a_mult, sig_raw(v1 * a_scale), a_add);
            v2 = fmaf(a_mult, sig_raw(v2 * a_scale), a_add);
            v3 = fmaf(a_mult, sig_raw(v3 * a_scale), a_add);

            float s1 = (q & 1) ? v0 : v1;
            float r1s = __shfl_xor_sync(0xffffffffu, s1, 1);
            float s2 = (q & 1) ? v2 : v3;
            float r2s = __shfl_xor_sync(0xffffffffu, s2, 1);
            float u0 = (q & 1) ? r1s : v0;
            float u1 = (q & 1) ? v1 : r1s;
            float u2 = (q & 1) ? r2s : v2;
            float u3 = (q & 1) ? v3 : r2s;
            float s3 = (q & 2) ? u0 : u2;
            float r3s = __shfl_xor_sync(0xffffffffu, s3, 2);
            float s4 = (q & 2) ? u1 : u3;
            float r4s = __shfl_xor_sync(0xffffffffu, s4, 2);
            float ti = (q & 2) ? r3s : u0;
            float tf = (q & 2) ? r4s : u1;
            float tg = (q & 2) ? u2 : r3s;
            float to = (q & 2) ? u3 : r4s;

            c = fmaf(tf, c, ti * tg);
            float h = to * tanh_f(c);
            if (jok) {
                float* pb = (q < 2) ? (float*)&sh_hA[wb][j] : (float*)&sh_hB[wb][j];
                pb[(q & 1) * 2 + layer] = h;
                if (layer == 0) {
                    ((float*)&sh_h0p[wb][j])[q] = h;
                } else {
                    outacc = fmaf(h, wl, outacc);
                }
            }
        }
        __syncthreads();
    }

    if (layer == 1 && jok) sh_red[q][j] = outacc;
    __syncthreads();
    if (tid < NB) {
        float s = b_lin[0];
#pragma unroll
        for (int jj = 0; jj < NHID; jj++) s += sh_red[tid][jj];
        out[b0 + tid] = s;
    }
}

// ---------------------------------------------------------------------------
// Entry point: two launches
// ---------------------------------------------------------------------------
extern "C" void kernel_launch(void* const* d_in, const int* in_sizes, int n_in,
                              void* d_out, int out_size)
{
    const float* x      = (const float*)d_in[0];
    const float* w_ih0  = (const float*)d_in[1];
    const float* w_hh0  = (const float*)d_in[2];
    const float* b_ih0  = (const float*)d_in[3];
    const float* b_hh0  = (const float*)d_in[4];
    const float* w_ih1  = (const float*)d_in[5];
    const float* w_hh1  = (const float*)d_in[6];
    const float* b_ih1  = (const float*)d_in[7];
    const float* b_hh1  = (const float*)d_in[8];
    const float* w_lin  = (const float*)d_in[9];
    const float* b_lin  = (const float*)d_in[10];
    float* out = (float*)d_out;

    gemm_xg0_tc<<<MROWS / 128, 256>>>(x, w_ih0, b_ih0, b_hh0);
    lstm_rec<<<BATCH / NB, 256>>>(w_hh0, w_ih1, w_hh1, b_ih1, b_hh1, w_lin, b_lin, out);
}